// round 6
// baseline (speedup 1.0000x reference)
#include <cuda_runtime.h>
#include <math.h>

#define BB 4
#define NN 4096
#define CC 64
#define ALPHA 0.2f
#define G  128          // scan chunks per batch
#define CH 32           // elements per chunk (NN = G*CH)
#define FULL 0xffffffffu

// ---------------- scratch (static device globals; no allocation) ----------------
__device__ float g_h[BB*NN*CC];        // h = feat @ W
__device__ float g_s1[BB*NN];
__device__ float g_s2[BB*NN];
__device__ float g_M2[BB];
__device__ float g_sval[BB*NN];        // sorted s2 (ascending) per batch
__device__ int   g_sidx[BB*NN];        // permutation
__device__ float g_E1[BB*NN];          // exp(sval - M2)
__device__ float g_E2[BB*NN];          // exp(alpha * sval)
__device__ float g_SgeH[BB*(NN+1)*CC]; // suffix sums of E1*h (sorted order)
__device__ float g_SltH[BB*(NN+1)*CC]; // prefix sums of E2*h (sorted order)
__device__ float g_Sge1[BB*(NN+1)];
__device__ float g_Slt1[BB*(NN+1)];
// scan intermediates
__device__ float g_pl [BB*G*CC], g_pg [BB*G*CC];  // chunk partials (vector)
__device__ float g_pls[BB*G],    g_pgs[BB*G];     // chunk partials (scalar)

// ---------------- K1: h = feat @ W, s1 = h.a1, s2 = h.a2 ----------------
__global__ __launch_bounds__(256) void k1_hsw(const float* __restrict__ feat,
                                              const float* __restrict__ W,
                                              const float* __restrict__ a)
{
    __shared__ float Ws[64*64];
    __shared__ float a1s[64], a2s[64];
    __shared__ float fs[4][64];
    __shared__ float p1[4][2], p2[4][2];

    int tid = threadIdx.x;                 // 256
    for (int i = tid; i < 64*64; i += 256) Ws[i] = W[i];
    if (tid < 64) { a1s[tid] = a[tid]; a2s[tid] = a[64 + tid]; }

    int rb = tid >> 6;                     // 0..3
    int c  = tid & 63;

    #pragma unroll
    for (int r = 0; r < 4; r++) {
        int row = blockIdx.x * 16 + r * 4 + rb;
        fs[rb][c] = feat[row*64 + c];
        __syncthreads();

        float acc0 = 0.f, acc1 = 0.f;
        #pragma unroll
        for (int k = 0; k < 64; k += 2) {
            acc0 = fmaf(fs[rb][k],   Ws[k*64 + c],     acc0);
            acc1 = fmaf(fs[rb][k+1], Ws[(k+1)*64 + c], acc1);
        }
        float acc = acc0 + acc1;
        g_h[row*64 + c] = acc;

        float v1 = acc * a1s[c];
        float v2 = acc * a2s[c];
        #pragma unroll
        for (int o = 16; o > 0; o >>= 1) {
            v1 += __shfl_down_sync(FULL, v1, o);
            v2 += __shfl_down_sync(FULL, v2, o);
        }
        if ((c & 31) == 0) { p1[rb][c>>5] = v1; p2[rb][c>>5] = v2; }
        __syncthreads();
        if (c == 0) {
            g_s1[row] = p1[rb][0] + p1[rb][1];
            g_s2[row] = p2[rb][0] + p2[rb][1];
        }
    }
}

// ---------------- K2: register-blocked bitonic sort (packed u64 key|idx) ----------------
__device__ __forceinline__ void cswap2(unsigned long long r[4], int m0, int m1, bool asc)
{
    unsigned long long a = r[m0], b = r[m1];
    bool sw = asc ? (a > b) : (a < b);
    if (sw) { r[m0] = b; r[m1] = a; }
}

// merge step for stage k: shuffle passes for j = jstart..4, then in-thread j=2,1.
__device__ __forceinline__ void warp_merge(unsigned long long r[4], int base, int k, int jstart)
{
    for (int j = jstart; j >= 4; j >>= 1) {
        int d = j >> 2;                       // lane distance
        #pragma unroll
        for (int m = 0; m < 4; m++) {
            unsigned long long pv = __shfl_xor_sync(FULL, r[m], d);
            int i = base + m;
            bool keepmin = (((i & k) == 0) == ((i & j) == 0));
            bool pless   = pv < r[m];
            r[m] = (keepmin == pless) ? pv : r[m];
        }
    }
    bool a = ((base & k) == 0);               // uniform per thread for k >= 4
    cswap2(r, 0, 2, a); cswap2(r, 1, 3, a);
    cswap2(r, 0, 1, a); cswap2(r, 2, 3, a);
}

__global__ __launch_bounds__(1024) void k2_sort()
{
    int b = blockIdx.x;
    __shared__ unsigned long long sp[NN];     // 32 KB
    int tid  = threadIdx.x;                   // 1024
    int base = tid * 4;

    // load 4 consecutive elements straight into registers, packed sortable
    unsigned long long r[4];
    #pragma unroll
    for (int m = 0; m < 4; m++) {
        int i = base + m;
        unsigned u   = __float_as_uint(g_s2[b*NN + i]);
        unsigned key = (u & 0x80000000u) ? ~u : (u | 0x80000000u);
        r[m] = ((unsigned long long)key << 32) | (unsigned)i;
    }

    // stages k=2..128: fully in registers / warp shuffles (no barriers)
    cswap2(r, 0, 1, true); cswap2(r, 2, 3, false);   // k=2
    #pragma unroll
    for (int k = 4; k <= 128; k <<= 1)
        warp_merge(r, base, k, k >> 1);

    #pragma unroll
    for (int m = 0; m < 4; m++) sp[base + m] = r[m];
    __syncthreads();

    // stages k=256..4096: smem passes for j>=128, register tail for j<=64
    for (int k = 256; k <= NN; k <<= 1) {
        for (int j = k >> 1; j >= 128; j >>= 1) {
            #pragma unroll
            for (int m = 0; m < 4; m++) {
                int i = base + m;
                int ixj = i ^ j;
                if (ixj > i) {
                    unsigned long long va = sp[i], vb = sp[ixj];
                    bool asc = ((i & k) == 0);
                    bool sw  = asc ? (va > vb) : (va < vb);
                    if (sw) { sp[i] = vb; sp[ixj] = va; }
                }
            }
            __syncthreads();
        }
        #pragma unroll
        for (int m = 0; m < 4; m++) r[m] = sp[base + m];
        warp_merge(r, base, k, 64);
        #pragma unroll
        for (int m = 0; m < 4; m++) sp[base + m] = r[m];
        __syncthreads();
    }

    // unpack max (last element), write tables
    {
        unsigned hiM = (unsigned)(sp[NN-1] >> 32);
        unsigned uM  = (hiM & 0x80000000u) ? (hiM ^ 0x80000000u) : ~hiM;
        float M2 = __uint_as_float(uM);
        if (tid == 0) g_M2[b] = M2;

        for (int i = tid; i < NN; i += 1024) {
            unsigned long long p = sp[i];
            unsigned hi = (unsigned)(p >> 32);
            unsigned u  = (hi & 0x80000000u) ? (hi ^ 0x80000000u) : ~hi;
            float v = __uint_as_float(u);
            g_sval[b*NN + i] = v;
            g_sidx[b*NN + i] = (int)(p & 0xffffffffu);
            g_E1[b*NN + i] = __expf(v - M2);
            g_E2[b*NN + i] = __expf(ALPHA * v);
        }
    }
}

// ---------------- K3a: chunk partial sums (grid = BB*G/4, block = 256) ----------------
__global__ __launch_bounds__(256) void k3a_partial()
{
    int tid = threadIdx.x;
    int rb  = tid >> 6;                   // chunk within block
    int c   = tid & 63;
    int bg  = blockIdx.x * 4 + rb;        // b*G + g
    int b   = bg >> 7;
    int g   = bg & (G-1);
    int base = g * CH;

    const float* hB   = g_h    + (size_t)b*NN*CC;
    const int*   sidx = g_sidx + b*NN;
    const float* E1   = g_E1   + b*NN;
    const float* E2   = g_E2   + b*NN;

    float accL = 0.f, accG = 0.f;
    #pragma unroll
    for (int k = base; k < base + CH; k++) {
        float hv = hB[(size_t)sidx[k]*64 + c];
        accL = fmaf(E2[k], hv, accL);
        accG = fmaf(E1[k], hv, accG);
    }
    g_pl[(size_t)bg*64 + c] = accL;
    g_pg[(size_t)bg*64 + c] = accG;

    // scalar chunk sums: within each 64-thread group, warp0 sums E2, warp1 sums E1
    int w = (tid >> 5) & 1, l = tid & 31;
    float e = (w == 0) ? E2[base + l] : E1[base + l];
    #pragma unroll
    for (int o = 16; o > 0; o >>= 1) e += __shfl_down_sync(FULL, e, o);
    if (l == 0) {
        if (w == 0) g_pls[bg] = e; else g_pgs[bg] = e;
    }
}

// ---------------- K3c: offsets (recomputed in-block) + write scan tables ----------------
__global__ __launch_bounds__(256) void k3c_tables()
{
    int tid = threadIdx.x;
    int rb  = tid >> 6;
    int c   = tid & 63;
    int bg  = blockIdx.x * 4 + rb;
    int b   = bg >> 7;
    int g   = bg & (G-1);
    int base = g * CH;

    // recompute this chunk's offsets by sweeping all chunk partials (L2-hot)
    float acc  = 0.f, accs  = 0.f;   // prefix  (lt, E2)
    float accg = 0.f, accgs = 0.f;   // suffix  (ge, E1)
    for (int g2 = 0; g2 < G; g2++) {
        size_t idx = (size_t)(b*G + g2)*64 + c;
        float pl = g_pl[idx];
        float pg = g_pg[idx];
        if (g2 < g) acc  += pl;
        if (g2 > g) accg += pg;
        if (c == 0) {
            float pls = g_pls[b*G + g2];
            float pgs = g_pgs[b*G + g2];
            if (g2 < g) accs  += pls;
            if (g2 > g) accgs += pgs;
        }
    }

    const float* hB   = g_h    + (size_t)b*NN*CC;
    const int*   sidx = g_sidx + b*NN;
    const float* E1   = g_E1   + b*NN;
    const float* E2   = g_E2   + b*NN;
    float* SltH = g_SltH + (size_t)b*(NN+1)*CC;
    float* SgeH = g_SgeH + (size_t)b*(NN+1)*CC;
    float* Slt1 = g_Slt1 + b*(NN+1);
    float* Sge1 = g_Sge1 + b*(NN+1);

    // prefix (lt branch, E2), exclusive
    #pragma unroll
    for (int k = base; k < base + CH; k++) {
        SltH[(size_t)k*64 + c] = acc;
        if (c == 0) Slt1[k] = accs;
        float hv = hB[(size_t)sidx[k]*64 + c];
        float e2 = E2[k];
        acc = fmaf(e2, hv, acc);
        if (c == 0) accs += e2;
    }
    if (g == G-1) { SltH[(size_t)NN*64 + c] = acc; if (c == 0) Slt1[NN] = accs; }

    // suffix (ge branch, E1), inclusive from k
    if (g == G-1) { SgeH[(size_t)NN*64 + c] = 0.f; if (c == 0) Sge1[NN] = 0.f; }
    #pragma unroll
    for (int k = base + CH - 1; k >= base; k--) {
        float hv = hB[(size_t)sidx[k]*64 + c];
        float e1 = E1[k];
        accg = fmaf(e1, hv, accg);
        SgeH[(size_t)k*64 + c] = accg;
        if (c == 0) { accgs += e1; Sge1[k] = accgs; }
    }
}

// ---------------- K4: per-row threshold lookup + combine ----------------
__global__ void k4_out(float* __restrict__ out)
{
    int gw   = (blockIdx.x * blockDim.x + threadIdx.x) >> 5;
    int lane = threadIdx.x & 31;
    if (gw >= BB*NN) return;
    int b = gw >> 12;

    float s1v = g_s1[gw];
    float M2  = g_M2[b];
    float thr = -s1v;

    // lower_bound: first index with sval >= thr (uniform across warp)
    const float* sval = g_sval + b*NN;
    int lo = 0, hi = NN;
    while (lo < hi) {
        int mid = (lo + hi) >> 1;
        if (sval[mid] < thr) lo = mid + 1; else hi = mid;
    }
    int k = lo;

    float x = s1v + M2;
    float m = (x >= 0.f) ? x : ALPHA * x;       // row max of lrelu logits
    float cge = __expf(x - m);                  // pairs with E1 = exp(s2 - M2)
    float clt = __expf(ALPHA * s1v - m);        // pairs with E2 = exp(alpha*s2)

    const float* SgeH = g_SgeH + ((size_t)b*(NN+1) + k)*64;
    const float* SltH = g_SltH + ((size_t)b*(NN+1) + k)*64;
    float denom = cge * g_Sge1[b*(NN+1) + k] + clt * g_Slt1[b*(NN+1) + k];
    float inv = 1.f / denom;

    float ge0 = SgeH[2*lane],   ge1 = SgeH[2*lane+1];
    float lt0 = SltH[2*lane],   lt1 = SltH[2*lane+1];
    float o0 = (cge*ge0 + clt*lt0) * inv;
    float o1 = (cge*ge1 + clt*lt1) * inv;

    float2* op = (float2*)(out + (size_t)gw*64);
    op[lane] = make_float2(o0, o1);
}

// ---------------- launch ----------------
extern "C" void kernel_launch(void* const* d_in, const int* in_sizes, int n_in,
                              void* d_out, int out_size)
{
    const float* feat = (const float*)d_in[0];
    // d_in[1] = adj: unused by the reference computation — deliberately not read.
    const float* W    = (const float*)d_in[2];
    const float* a    = (const float*)d_in[3];
    float* out = (float*)d_out;

    k1_hsw<<<(BB*NN)/16, 256>>>(feat, W, a);
    k2_sort<<<BB, 1024>>>();
    k3a_partial<<<BB*G/4, 256>>>();
    k3c_tables<<<BB*G/4, 256>>>();
    k4_out<<<(BB*NN*32)/256, 256>>>(out);
}

// round 7
// speedup vs baseline: 1.7113x; 1.7113x over previous
#include <cuda_runtime.h>
#include <math.h>

#define BB 4
#define NN 4096
#define CC 64
#define ALPHA 0.2f
#define G  256          // scan chunks per batch
#define CH 16           // elements per chunk (NN = G*CH)
#define FULL 0xffffffffu

// ---------------- scratch (static device globals; no allocation) ----------------
__device__ __align__(16) float g_h[BB*NN*CC];        // h = feat @ W
__device__ __align__(16) float g_s1[BB*NN];
__device__ __align__(16) float g_s2[BB*NN];
__device__ float g_M2[BB];
__device__ __align__(16) float g_sval[BB*NN];        // sorted s2 (ascending) per batch
__device__ __align__(16) int   g_sidx[BB*NN];        // permutation
__device__ __align__(16) float g_E1[BB*NN];          // exp(sval - M2)
__device__ __align__(16) float g_E2[BB*NN];          // exp(alpha * sval)
__device__ __align__(16) float g_SgeH[BB*(NN+1)*CC]; // suffix sums of E1*h
__device__ __align__(16) float g_SltH[BB*(NN+1)*CC]; // prefix sums of E2*h
__device__ __align__(16) float g_Sge1[BB*(NN+1)];
__device__ __align__(16) float g_Slt1[BB*(NN+1)];
// scan intermediates
__device__ __align__(16) float g_pl [BB*G*CC], g_pg [BB*G*CC];  // chunk partials
__device__ __align__(16) float g_ofL[BB*G*CC], g_ofG[BB*G*CC];  // chunk offsets
__device__ float g_ofLs[BB*G], g_ofGs[BB*G];                    // scalar offsets

// ---------------- K1: h = feat @ W, s1 = h.a1, s2 = h.a2 ----------------
__global__ __launch_bounds__(256) void k1_hsw(const float* __restrict__ feat,
                                              const float* __restrict__ W,
                                              const float* __restrict__ a)
{
    __shared__ float Ws[64*64];
    __shared__ float a1s[64], a2s[64];
    __shared__ float fs[4][64];
    __shared__ float p1[4][2], p2[4][2];

    int tid = threadIdx.x;                 // 256
    for (int i = tid; i < 64*64; i += 256) Ws[i] = W[i];
    if (tid < 64) { a1s[tid] = a[tid]; a2s[tid] = a[64 + tid]; }

    int rb = tid >> 6;                     // 0..3
    int c  = tid & 63;

    #pragma unroll
    for (int r = 0; r < 4; r++) {
        int row = blockIdx.x * 16 + r * 4 + rb;
        fs[rb][c] = feat[row*64 + c];
        __syncthreads();

        float acc0 = 0.f, acc1 = 0.f;
        #pragma unroll
        for (int k = 0; k < 64; k += 2) {
            acc0 = fmaf(fs[rb][k],   Ws[k*64 + c],     acc0);
            acc1 = fmaf(fs[rb][k+1], Ws[(k+1)*64 + c], acc1);
        }
        float acc = acc0 + acc1;
        g_h[row*64 + c] = acc;

        float v1 = acc * a1s[c];
        float v2 = acc * a2s[c];
        #pragma unroll
        for (int o = 16; o > 0; o >>= 1) {
            v1 += __shfl_down_sync(FULL, v1, o);
            v2 += __shfl_down_sync(FULL, v2, o);
        }
        if ((c & 31) == 0) { p1[rb][c>>5] = v1; p2[rb][c>>5] = v2; }
        __syncthreads();
        if (c == 0) {
            g_s1[row] = p1[rb][0] + p1[rb][1];
            g_s2[row] = p2[rb][0] + p2[rb][1];
        }
    }
}

// ---------------- K2: register-blocked bitonic sort (packed u64 key|idx) ----------------
__device__ __forceinline__ void cswap2(unsigned long long r[4], int m0, int m1, bool asc)
{
    unsigned long long a = r[m0], b = r[m1];
    bool sw = asc ? (a > b) : (a < b);
    if (sw) { r[m0] = b; r[m1] = a; }
}

__device__ __forceinline__ void warp_merge(unsigned long long r[4], int base, int k, int jstart)
{
    for (int j = jstart; j >= 4; j >>= 1) {
        int d = j >> 2;                       // lane distance
        #pragma unroll
        for (int m = 0; m < 4; m++) {
            unsigned long long pv = __shfl_xor_sync(FULL, r[m], d);
            int i = base + m;
            bool keepmin = (((i & k) == 0) == ((i & j) == 0));
            bool pless   = pv < r[m];
            r[m] = (keepmin == pless) ? pv : r[m];
        }
    }
    bool a = ((base & k) == 0);               // uniform per thread for k >= 4
    cswap2(r, 0, 2, a); cswap2(r, 1, 3, a);
    cswap2(r, 0, 1, a); cswap2(r, 2, 3, a);
}

__global__ __launch_bounds__(1024) void k2_sort()
{
    int b = blockIdx.x;
    __shared__ unsigned long long sp[NN];     // 32 KB
    int tid  = threadIdx.x;                   // 1024
    int base = tid * 4;

    unsigned long long r[4];
    #pragma unroll
    for (int m = 0; m < 4; m++) {
        int i = base + m;
        unsigned u   = __float_as_uint(g_s2[b*NN + i]);
        unsigned key = (u & 0x80000000u) ? ~u : (u | 0x80000000u);
        r[m] = ((unsigned long long)key << 32) | (unsigned)i;
    }

    cswap2(r, 0, 1, true); cswap2(r, 2, 3, false);   // k=2
    #pragma unroll
    for (int k = 4; k <= 128; k <<= 1)
        warp_merge(r, base, k, k >> 1);

    #pragma unroll
    for (int m = 0; m < 4; m++) sp[base + m] = r[m];
    __syncthreads();

    for (int k = 256; k <= NN; k <<= 1) {
        for (int j = k >> 1; j >= 128; j >>= 1) {
            #pragma unroll
            for (int m = 0; m < 4; m++) {
                int i = base + m;
                int ixj = i ^ j;
                if (ixj > i) {
                    unsigned long long va = sp[i], vb = sp[ixj];
                    bool asc = ((i & k) == 0);
                    bool sw  = asc ? (va > vb) : (va < vb);
                    if (sw) { sp[i] = vb; sp[ixj] = va; }
                }
            }
            __syncthreads();
        }
        #pragma unroll
        for (int m = 0; m < 4; m++) r[m] = sp[base + m];
        warp_merge(r, base, k, 64);
        #pragma unroll
        for (int m = 0; m < 4; m++) sp[base + m] = r[m];
        __syncthreads();
    }

    {
        unsigned hiM = (unsigned)(sp[NN-1] >> 32);
        unsigned uM  = (hiM & 0x80000000u) ? (hiM ^ 0x80000000u) : ~hiM;
        float M2 = __uint_as_float(uM);
        if (tid == 0) g_M2[b] = M2;

        for (int i = tid; i < NN; i += 1024) {
            unsigned long long p = sp[i];
            unsigned hi = (unsigned)(p >> 32);
            unsigned u  = (hi & 0x80000000u) ? (hi ^ 0x80000000u) : ~hi;
            float v = __uint_as_float(u);
            g_sval[b*NN + i] = v;
            g_sidx[b*NN + i] = (int)(p & 0xffffffffu);
            g_E1[b*NN + i] = __expf(v - M2);
            g_E2[b*NN + i] = __expf(ALPHA * v);
        }
    }
}

// ---------------- K3a: chunk partial sums (grid = BB*G/8, block = 128) ----------------
// 16 threads per chunk, float4 channels.
__global__ __launch_bounds__(128) void k3a_partial()
{
    int tid = threadIdx.x;
    int rb  = tid >> 4;                    // chunk in block (0..7)
    int c4  = tid & 15;                    // float4 channel group
    int bg  = blockIdx.x * 8 + rb;         // b*G + g
    int b   = bg >> 8;
    int g   = bg & (G-1);
    int base = g * CH;

    const float4* hB4  = (const float4*)g_h + (size_t)b*NN*16;
    const int*    sidx = g_sidx + b*NN;
    const float*  E1   = g_E1   + b*NN;
    const float*  E2   = g_E2   + b*NN;

    float4 aL = make_float4(0.f,0.f,0.f,0.f);
    float4 aG = make_float4(0.f,0.f,0.f,0.f);
    #pragma unroll
    for (int k = base; k < base + CH; k++) {
        float4 hv = hB4[(size_t)sidx[k]*16 + c4];
        float e2 = E2[k], e1 = E1[k];
        aL.x = fmaf(e2, hv.x, aL.x); aL.y = fmaf(e2, hv.y, aL.y);
        aL.z = fmaf(e2, hv.z, aL.z); aL.w = fmaf(e2, hv.w, aL.w);
        aG.x = fmaf(e1, hv.x, aG.x); aG.y = fmaf(e1, hv.y, aG.y);
        aG.z = fmaf(e1, hv.z, aG.z); aG.w = fmaf(e1, hv.w, aG.w);
    }
    ((float4*)g_pl)[(size_t)bg*16 + c4] = aL;
    ((float4*)g_pg)[(size_t)bg*16 + c4] = aG;
}

// ---------------- K3b: parallel scan over G=256 chunk partials ----------------
// grid = BB*17: 16 float4-channel-group blocks + 1 scalar block per batch. block=256.
__global__ __launch_bounds__(256) void k3b_offsets()
{
    int bx = blockIdx.x;
    int b  = bx / 17;
    int cg = bx % 17;
    int g  = threadIdx.x;                 // 0..255 (one per chunk)

    __shared__ float4 s4[G];              // 4 KB

    if (cg < 16) {
        // vector groups
        float4 pl = ((const float4*)g_pl)[(size_t)(b*G + g)*16 + cg];
        s4[g] = pl; __syncthreads();
        #pragma unroll
        for (int off = 1; off < G; off <<= 1) {
            float4 v = (g >= off) ? s4[g - off] : make_float4(0.f,0.f,0.f,0.f);
            __syncthreads();
            s4[g].x += v.x; s4[g].y += v.y; s4[g].z += v.z; s4[g].w += v.w;
            __syncthreads();
        }
        float4 ofL = (g > 0) ? s4[g-1] : make_float4(0.f,0.f,0.f,0.f);
        __syncthreads();

        float4 pg = ((const float4*)g_pg)[(size_t)(b*G + g)*16 + cg];
        s4[g] = pg; __syncthreads();
        #pragma unroll
        for (int off = 1; off < G; off <<= 1) {
            float4 v = (g + off < G) ? s4[g + off] : make_float4(0.f,0.f,0.f,0.f);
            __syncthreads();
            s4[g].x += v.x; s4[g].y += v.y; s4[g].z += v.z; s4[g].w += v.w;
            __syncthreads();
        }
        float4 ofG = (g < G-1) ? s4[g+1] : make_float4(0.f,0.f,0.f,0.f);

        ((float4*)g_ofL)[(size_t)(b*G + g)*16 + cg] = ofL;
        ((float4*)g_ofG)[(size_t)(b*G + g)*16 + cg] = ofG;
    } else {
        // scalar e-sums: compute per-chunk sums directly from contiguous E arrays
        float* ss = (float*)s4;
        const float4* E2v = (const float4*)(g_E2 + b*NN);
        const float4* E1v = (const float4*)(g_E1 + b*NN);
        float pls = 0.f, pgs = 0.f;
        #pragma unroll
        for (int m = 0; m < CH/4; m++) {
            float4 e2 = E2v[g*(CH/4) + m];
            float4 e1 = E1v[g*(CH/4) + m];
            pls += (e2.x + e2.y) + (e2.z + e2.w);
            pgs += (e1.x + e1.y) + (e1.z + e1.w);
        }
        ss[g] = pls; __syncthreads();
        #pragma unroll
        for (int off = 1; off < G; off <<= 1) {
            float v = (g >= off) ? ss[g - off] : 0.f;
            __syncthreads();
            ss[g] += v;
            __syncthreads();
        }
        float ofLs = (g > 0) ? ss[g-1] : 0.f;
        __syncthreads();
        ss[g] = pgs; __syncthreads();
        #pragma unroll
        for (int off = 1; off < G; off <<= 1) {
            float v = (g + off < G) ? ss[g + off] : 0.f;
            __syncthreads();
            ss[g] += v;
            __syncthreads();
        }
        float ofGs = (g < G-1) ? ss[g+1] : 0.f;
        g_ofLs[b*G + g] = ofLs;
        g_ofGs[b*G + g] = ofGs;
    }
}

// ---------------- K3c: write scan tables. grid = 2*BB*G/8: first half prefix, second suffix ----
__global__ __launch_bounds__(128) void k3c_tables()
{
    const int half = BB*G/8;              // 128 blocks per role
    bool suffix = (blockIdx.x >= half);
    int blk = suffix ? (blockIdx.x - half) : blockIdx.x;

    int tid = threadIdx.x;
    int rb  = tid >> 4;
    int c4  = tid & 15;
    int bg  = blk * 8 + rb;
    int b   = bg >> 8;
    int g   = bg & (G-1);
    int base = g * CH;

    const float4* hB4  = (const float4*)g_h + (size_t)b*NN*16;
    const int*    sidx = g_sidx + b*NN;

    if (!suffix) {
        const float* E2 = g_E2 + b*NN;
        float4* SltH4 = (float4*)g_SltH + (size_t)b*(NN+1)*16;
        float*  Slt1  = g_Slt1 + b*(NN+1);
        float4 acc  = ((const float4*)g_ofL)[(size_t)bg*16 + c4];
        float  accs = g_ofLs[bg];
        #pragma unroll
        for (int k = base; k < base + CH; k++) {
            SltH4[(size_t)k*16 + c4] = acc;
            if (c4 == 0) Slt1[k] = accs;
            float  e2 = E2[k];
            float4 hv = hB4[(size_t)sidx[k]*16 + c4];
            acc.x = fmaf(e2, hv.x, acc.x); acc.y = fmaf(e2, hv.y, acc.y);
            acc.z = fmaf(e2, hv.z, acc.z); acc.w = fmaf(e2, hv.w, acc.w);
            accs += e2;
        }
        if (g == G-1) {
            SltH4[(size_t)NN*16 + c4] = acc;
            if (c4 == 0) Slt1[NN] = accs;
        }
    } else {
        const float* E1 = g_E1 + b*NN;
        float4* SgeH4 = (float4*)g_SgeH + (size_t)b*(NN+1)*16;
        float*  Sge1  = g_Sge1 + b*(NN+1);
        float4 acc  = ((const float4*)g_ofG)[(size_t)bg*16 + c4];
        float  accs = g_ofGs[bg];
        if (g == G-1) {
            SgeH4[(size_t)NN*16 + c4] = make_float4(0.f,0.f,0.f,0.f);
            if (c4 == 0) Sge1[NN] = 0.f;
        }
        #pragma unroll
        for (int k = base + CH - 1; k >= base; k--) {
            float  e1 = E1[k];
            float4 hv = hB4[(size_t)sidx[k]*16 + c4];
            acc.x = fmaf(e1, hv.x, acc.x); acc.y = fmaf(e1, hv.y, acc.y);
            acc.z = fmaf(e1, hv.z, acc.z); acc.w = fmaf(e1, hv.w, acc.w);
            accs += e1;
            SgeH4[(size_t)k*16 + c4] = acc;
            if (c4 == 0) Sge1[k] = accs;
        }
    }
}

// ---------------- K4: per-row threshold lookup + combine ----------------
__global__ void k4_out(float* __restrict__ out)
{
    int gw   = (blockIdx.x * blockDim.x + threadIdx.x) >> 5;
    int lane = threadIdx.x & 31;
    if (gw >= BB*NN) return;
    int b = gw >> 12;

    float s1v = g_s1[gw];
    float M2  = g_M2[b];
    float thr = -s1v;

    const float* sval = g_sval + b*NN;
    int lo = 0, hi = NN;
    while (lo < hi) {
        int mid = (lo + hi) >> 1;
        if (sval[mid] < thr) lo = mid + 1; else hi = mid;
    }
    int k = lo;

    float x = s1v + M2;
    float m = (x >= 0.f) ? x : ALPHA * x;       // row max of lrelu logits
    float cge = __expf(x - m);                  // pairs with E1 = exp(s2 - M2)
    float clt = __expf(ALPHA * s1v - m);        // pairs with E2 = exp(alpha*s2)

    const float* SgeH = g_SgeH + ((size_t)b*(NN+1) + k)*64;
    const float* SltH = g_SltH + ((size_t)b*(NN+1) + k)*64;
    float denom = cge * g_Sge1[b*(NN+1) + k] + clt * g_Slt1[b*(NN+1) + k];
    float inv = 1.f / denom;

    float ge0 = SgeH[2*lane],   ge1 = SgeH[2*lane+1];
    float lt0 = SltH[2*lane],   lt1 = SltH[2*lane+1];
    float o0 = (cge*ge0 + clt*lt0) * inv;
    float o1 = (cge*ge1 + clt*lt1) * inv;

    float2* op = (float2*)(out + (size_t)gw*64);
    op[lane] = make_float2(o0, o1);
}

// ---------------- launch ----------------
extern "C" void kernel_launch(void* const* d_in, const int* in_sizes, int n_in,
                              void* d_out, int out_size)
{
    const float* feat = (const float*)d_in[0];
    // d_in[1] = adj: unused by the reference computation — deliberately not read.
    const float* W    = (const float*)d_in[2];
    const float* a    = (const float*)d_in[3];
    float* out = (float*)d_out;

    k1_hsw<<<(BB*NN)/16, 256>>>(feat, W, a);
    k2_sort<<<BB, 1024>>>();
    k3a_partial<<<BB*G/8, 128>>>();
    k3b_offsets<<<BB*17, 256>>>();
    k3c_tables<<<2*BB*G/8, 128>>>();
    k4_out<<<(BB*NN*32)/256, 256>>>(out);
}

// round 9
// speedup vs baseline: 2.0483x; 1.1969x over previous
#include <cuda_runtime.h>
#include <math.h>

#define BB 4
#define NN 4096
#define CC 64
#define ALPHA 0.2f
#define G  256          // scan chunks per batch
#define CH 16           // elements per chunk (NN = G*CH)
#define RUN 512         // sort run length
#define NRUN 8          // runs per batch
#define FULL 0xffffffffu

// ---------------- scratch (static device globals; no allocation) ----------------
__device__ __align__(16) float g_h[BB*NN*CC];        // h = feat @ W
__device__ __align__(16) float g_s1[BB*NN];
__device__ __align__(16) float g_s2[BB*NN];
__device__ float g_M2[BB];
__device__ __align__(16) float g_sval[BB*NN];        // sorted s2 (ascending) per batch
__device__ __align__(16) int   g_sidx[BB*NN];        // permutation
__device__ __align__(16) float g_E1[BB*NN];          // exp(sval - M2)
__device__ __align__(16) float g_E2[BB*NN];          // exp(alpha * sval)
__device__ __align__(16) unsigned long long g_runs[BB*NN]; // sorted runs (packed key|idx)
__device__ __align__(16) float g_SgeH[BB*(NN+1)*CC]; // suffix sums of E1*h
__device__ __align__(16) float g_SltH[BB*(NN+1)*CC]; // prefix sums of E2*h
__device__ __align__(16) float g_Sge1[BB*(NN+1)];
__device__ __align__(16) float g_Slt1[BB*(NN+1)];
// scan intermediates
__device__ __align__(16) float g_pl [BB*G*CC], g_pg [BB*G*CC];  // chunk partials
__device__ __align__(16) float g_ofL[BB*G*CC], g_ofG[BB*G*CC];  // chunk offsets
__device__ float g_ofLs[BB*G], g_ofGs[BB*G];                    // scalar offsets

// ---------------- K1: h = feat @ W, s1 = h.a1, s2 = h.a2 ----------------
__global__ __launch_bounds__(256) void k1_hsw(const float* __restrict__ feat,
                                              const float* __restrict__ W,
                                              const float* __restrict__ a)
{
    __shared__ float Ws[64*64];
    __shared__ float a1s[64], a2s[64];
    __shared__ float fs[4][64];
    __shared__ float p1[4][2], p2[4][2];

    int tid = threadIdx.x;                 // 256
    for (int i = tid; i < 64*64; i += 256) Ws[i] = W[i];
    if (tid < 64) { a1s[tid] = a[tid]; a2s[tid] = a[64 + tid]; }

    int rb = tid >> 6;                     // 0..3
    int c  = tid & 63;

    #pragma unroll
    for (int r = 0; r < 4; r++) {
        int row = blockIdx.x * 16 + r * 4 + rb;
        fs[rb][c] = feat[row*64 + c];
        __syncthreads();

        float acc0 = 0.f, acc1 = 0.f;
        #pragma unroll
        for (int k = 0; k < 64; k += 2) {
            acc0 = fmaf(fs[rb][k],   Ws[k*64 + c],     acc0);
            acc1 = fmaf(fs[rb][k+1], Ws[(k+1)*64 + c], acc1);
        }
        float acc = acc0 + acc1;
        g_h[row*64 + c] = acc;

        float v1 = acc * a1s[c];
        float v2 = acc * a2s[c];
        #pragma unroll
        for (int o = 16; o > 0; o >>= 1) {
            v1 += __shfl_down_sync(FULL, v1, o);
            v2 += __shfl_down_sync(FULL, v2, o);
        }
        if ((c & 31) == 0) { p1[rb][c>>5] = v1; p2[rb][c>>5] = v2; }
        __syncthreads();
        if (c == 0) {
            g_s1[row] = p1[rb][0] + p1[rb][1];
            g_s2[row] = p2[rb][0] + p2[rb][1];
        }
    }
}

// ---------------- bitonic helpers (packed u64 key|idx) ----------------
__device__ __forceinline__ void cswap2(unsigned long long r[4], int m0, int m1, bool asc)
{
    unsigned long long a = r[m0], b = r[m1];
    bool sw = asc ? (a > b) : (a < b);
    if (sw) { r[m0] = b; r[m1] = a; }
}

__device__ __forceinline__ void warp_merge(unsigned long long r[4], int base, int k, int jstart)
{
    for (int j = jstart; j >= 4; j >>= 1) {
        int d = j >> 2;                       // lane distance
        #pragma unroll
        for (int m = 0; m < 4; m++) {
            unsigned long long pv = __shfl_xor_sync(FULL, r[m], d);
            int i = base + m;
            bool keepmin = (((i & k) == 0) == ((i & j) == 0));
            bool pless   = pv < r[m];
            r[m] = (keepmin == pless) ? pv : r[m];
        }
    }
    bool a = ((base & k) == 0);               // uniform per thread for k >= 4
    cswap2(r, 0, 2, a); cswap2(r, 1, 3, a);
    cswap2(r, 0, 1, a); cswap2(r, 2, 3, a);
}

// ---------------- K2a: sort 512-element runs (grid = BB*NRUN, block = 128) -------------
__global__ __launch_bounds__(128) void k2a_sort_runs()
{
    int blk = blockIdx.x;                 // 0..31
    int b   = blk >> 3;
    int run = blk & 7;
    int tid = threadIdx.x;                // 128
    int base = tid * 4;                   // position within run
    int gbase = b*NN + run*RUN;

    __shared__ unsigned long long sp[RUN];

    unsigned long long r[4];
    #pragma unroll
    for (int m = 0; m < 4; m++) {
        int i = base + m;
        unsigned u   = __float_as_uint(g_s2[gbase + i]);
        unsigned key = (u & 0x80000000u) ? ~u : (u | 0x80000000u);
        r[m] = ((unsigned long long)key << 32) | (unsigned)(run*RUN + i);
    }

    // stages k=2..128 in registers / shuffles
    cswap2(r, 0, 1, true); cswap2(r, 2, 3, false);
    #pragma unroll
    for (int k = 4; k <= 128; k <<= 1)
        warp_merge(r, base, k, k >> 1);

    #pragma unroll
    for (int m = 0; m < 4; m++) sp[base + m] = r[m];
    __syncthreads();

    // stages k=256, 512: smem for j>=128, register tail
    for (int k = 256; k <= RUN; k <<= 1) {
        for (int j = k >> 1; j >= 128; j >>= 1) {
            #pragma unroll
            for (int m = 0; m < 4; m++) {
                int i = base + m;
                int ixj = i ^ j;
                if (ixj > i) {
                    unsigned long long va = sp[i], vb = sp[ixj];
                    bool asc = ((i & k) == 0);
                    bool sw  = asc ? (va > vb) : (va < vb);
                    if (sw) { sp[i] = vb; sp[ixj] = va; }
                }
            }
            __syncthreads();
        }
        #pragma unroll
        for (int m = 0; m < 4; m++) r[m] = sp[base + m];
        warp_merge(r, base, k, 64);
        #pragma unroll
        for (int m = 0; m < 4; m++) sp[base + m] = r[m];
        __syncthreads();
    }

    #pragma unroll
    for (int m = 0; m < 4; m++) g_runs[gbase + base + m] = sp[base + m];
}

// ---------------- K2b: global rank via binary search + scatter (grid = BB*NN/256) ------
__global__ __launch_bounds__(256) void k2b_rank()
{
    int gid = blockIdx.x * 256 + threadIdx.x;   // 0..BB*NN-1
    int b   = gid >> 12;
    int pos = gid & (NN-1);
    int run = pos >> 9;
    int loc = pos & (RUN-1);

    const unsigned long long* runs = g_runs + b*NN;
    unsigned long long pv = runs[pos];

    int rank = loc;
    #pragma unroll
    for (int r2 = 0; r2 < NRUN; r2++) {
        if (r2 == run) continue;
        const unsigned long long* R = runs + r2*RUN;
        int lo = 0, hi = RUN;
        #pragma unroll
        for (int s = 0; s < 10; s++) {         // interval 512 -> 0 needs 10 halvings
            if (lo < hi) {
                int mid = (lo + hi) >> 1;
                if (R[mid] < pv) lo = mid + 1; else hi = mid;
            }
        }
        rank += lo;
    }

    // M2 = max over the 8 run tails
    unsigned long long mx = runs[RUN-1];
    #pragma unroll
    for (int r2 = 1; r2 < NRUN; r2++) {
        unsigned long long t = runs[r2*RUN + RUN-1];
        if (t > mx) mx = t;
    }
    unsigned hiM = (unsigned)(mx >> 32);
    unsigned uM  = (hiM & 0x80000000u) ? (hiM ^ 0x80000000u) : ~hiM;
    float M2 = __uint_as_float(uM);
    if (pos == 0) g_M2[b] = M2;

    unsigned hk = (unsigned)(pv >> 32);
    unsigned uv = (hk & 0x80000000u) ? (hk ^ 0x80000000u) : ~hk;
    float v = __uint_as_float(uv);

    g_sval[b*NN + rank] = v;
    g_sidx[b*NN + rank] = (int)(pv & 0xffffffffu);
    g_E1[b*NN + rank] = __expf(v - M2);
    g_E2[b*NN + rank] = __expf(ALPHA * v);
}

// ---------------- K3a: chunk partial sums (grid = BB*G/8, block = 128) ----------------
__global__ __launch_bounds__(128) void k3a_partial()
{
    int tid = threadIdx.x;
    int rb  = tid >> 4;                    // chunk in block (0..7)
    int c4  = tid & 15;                    // float4 channel group
    int bg  = blockIdx.x * 8 + rb;         // b*G + g
    int b   = bg >> 8;
    int g   = bg & (G-1);
    int base = g * CH;

    const float4* hB4  = (const float4*)g_h + (size_t)b*NN*16;
    const int*    sidx = g_sidx + b*NN;
    const float*  E1   = g_E1   + b*NN;
    const float*  E2   = g_E2   + b*NN;

    float4 aL = make_float4(0.f,0.f,0.f,0.f);
    float4 aG = make_float4(0.f,0.f,0.f,0.f);
    #pragma unroll
    for (int k = base; k < base + CH; k++) {
        float4 hv = hB4[(size_t)sidx[k]*16 + c4];
        float e2 = E2[k], e1 = E1[k];
        aL.x = fmaf(e2, hv.x, aL.x); aL.y = fmaf(e2, hv.y, aL.y);
        aL.z = fmaf(e2, hv.z, aL.z); aL.w = fmaf(e2, hv.w, aL.w);
        aG.x = fmaf(e1, hv.x, aG.x); aG.y = fmaf(e1, hv.y, aG.y);
        aG.z = fmaf(e1, hv.z, aG.z); aG.w = fmaf(e1, hv.w, aG.w);
    }
    ((float4*)g_pl)[(size_t)bg*16 + c4] = aL;
    ((float4*)g_pg)[(size_t)bg*16 + c4] = aG;
}

// ---------------- K3b: warp-shuffle scans over G=256 chunk partials ----------------
__device__ __forceinline__ float4 warp_iscan4(float4 v, int lane)
{
    #pragma unroll
    for (int o = 1; o < 32; o <<= 1) {
        float ux = __shfl_up_sync(FULL, v.x, o);
        float uy = __shfl_up_sync(FULL, v.y, o);
        float uz = __shfl_up_sync(FULL, v.z, o);
        float uw = __shfl_up_sync(FULL, v.w, o);
        if (lane >= o) { v.x += ux; v.y += uy; v.z += uz; v.w += uw; }
    }
    return v;
}
__device__ __forceinline__ float warp_iscan1(float v, int lane)
{
    #pragma unroll
    for (int o = 1; o < 32; o <<= 1) {
        float u = __shfl_up_sync(FULL, v, o);
        if (lane >= o) v += u;
    }
    return v;
}

// grid = BB*17: 16 float4-channel-group blocks + 1 scalar block per batch. block=256.
__global__ __launch_bounds__(256) void k3b_offsets()
{
    int bx = blockIdx.x;
    int b  = bx / 17;
    int cg = bx % 17;
    int t  = threadIdx.x;                 // 0..255 (one per chunk)
    int lane = t & 31, w = t >> 5;        // 8 warps

    __shared__ float4 ws4[8];

    if (cg < 16) {
        // prefix over pl
        float4 pl = ((const float4*)g_pl)[(size_t)(b*G + t)*16 + cg];
        float4 v = warp_iscan4(pl, lane);
        if (lane == 31) ws4[w] = v;
        __syncthreads();
        float4 off = make_float4(0.f,0.f,0.f,0.f);
        for (int i = 0; i < w; i++) {
            float4 s = ws4[i];
            off.x += s.x; off.y += s.y; off.z += s.z; off.w += s.w;
        }
        float4 ofL = make_float4(v.x+off.x-pl.x, v.y+off.y-pl.y,
                                 v.z+off.z-pl.z, v.w+off.w-pl.w);
        ((float4*)g_ofL)[(size_t)(b*G + t)*16 + cg] = ofL;
        __syncthreads();

        // suffix over pg: scan reversed order
        int gr = G - 1 - t;
        float4 pg = ((const float4*)g_pg)[(size_t)(b*G + gr)*16 + cg];
        v = warp_iscan4(pg, lane);
        if (lane == 31) ws4[w] = v;
        __syncthreads();
        off = make_float4(0.f,0.f,0.f,0.f);
        for (int i = 0; i < w; i++) {
            float4 s = ws4[i];
            off.x += s.x; off.y += s.y; off.z += s.z; off.w += s.w;
        }
        float4 ofG = make_float4(v.x+off.x-pg.x, v.y+off.y-pg.y,
                                 v.z+off.z-pg.z, v.w+off.w-pg.w);
        ((float4*)g_ofG)[(size_t)(b*G + gr)*16 + cg] = ofG;
    } else {
        float* wss = (float*)ws4;
        const float4* E2v = (const float4*)(g_E2 + b*NN);
        const float4* E1v = (const float4*)(g_E1 + b*NN);

        // prefix of per-chunk E2 sums (chunk t)
        float pls = 0.f;
        #pragma unroll
        for (int m = 0; m < CH/4; m++) {
            float4 e2 = E2v[t*(CH/4) + m];
            pls += (e2.x + e2.y) + (e2.z + e2.w);
        }
        float v = warp_iscan1(pls, lane);
        if (lane == 31) wss[w] = v;
        __syncthreads();
        float off = 0.f;
        for (int i = 0; i < w; i++) off += wss[i];
        g_ofLs[b*G + t] = v + off - pls;
        __syncthreads();

        // suffix of per-chunk E1 sums (chunk gr)
        int gr = G - 1 - t;
        float pgs = 0.f;
        #pragma unroll
        for (int m = 0; m < CH/4; m++) {
            float4 e1 = E1v[gr*(CH/4) + m];
            pgs += (e1.x + e1.y) + (e1.z + e1.w);
        }
        v = warp_iscan1(pgs, lane);
        if (lane == 31) wss[w] = v;
        __syncthreads();
        off = 0.f;
        for (int i = 0; i < w; i++) off += wss[i];
        g_ofGs[b*G + gr] = v + off - pgs;
    }
}

// ---------------- K3c: write scan tables. grid = 2*BB*G/8: first half prefix, second suffix ----
__global__ __launch_bounds__(128) void k3c_tables()
{
    const int half = BB*G/8;              // 128 blocks per role
    bool suffix = (blockIdx.x >= half);
    int blk = suffix ? (blockIdx.x - half) : blockIdx.x;

    int tid = threadIdx.x;
    int rb  = tid >> 4;
    int c4  = tid & 15;
    int bg  = blk * 8 + rb;
    int b   = bg >> 8;
    int g   = bg & (G-1);
    int base = g * CH;

    const float4* hB4  = (const float4*)g_h + (size_t)b*NN*16;
    const int*    sidx = g_sidx + b*NN;

    if (!suffix) {
        const float* E2 = g_E2 + b*NN;
        float4* SltH4 = (float4*)g_SltH + (size_t)b*(NN+1)*16;
        float*  Slt1  = g_Slt1 + b*(NN+1);
        float4 acc  = ((const float4*)g_ofL)[(size_t)bg*16 + c4];
        float  accs = g_ofLs[bg];
        #pragma unroll
        for (int k = base; k < base + CH; k++) {
            SltH4[(size_t)k*16 + c4] = acc;
            if (c4 == 0) Slt1[k] = accs;
            float  e2 = E2[k];
            float4 hv = hB4[(size_t)sidx[k]*16 + c4];
            acc.x = fmaf(e2, hv.x, acc.x); acc.y = fmaf(e2, hv.y, acc.y);
            acc.z = fmaf(e2, hv.z, acc.z); acc.w = fmaf(e2, hv.w, acc.w);
            accs += e2;
        }
        if (g == G-1) {
            SltH4[(size_t)NN*16 + c4] = acc;
            if (c4 == 0) Slt1[NN] = accs;
        }
    } else {
        const float* E1 = g_E1 + b*NN;
        float4* SgeH4 = (float4*)g_SgeH + (size_t)b*(NN+1)*16;
        float*  Sge1  = g_Sge1 + b*(NN+1);
        float4 acc  = ((const float4*)g_ofG)[(size_t)bg*16 + c4];
        float  accs = g_ofGs[bg];
        if (g == G-1) {
            SgeH4[(size_t)NN*16 + c4] = make_float4(0.f,0.f,0.f,0.f);
            if (c4 == 0) Sge1[NN] = 0.f;
        }
        #pragma unroll
        for (int k = base + CH - 1; k >= base; k--) {
            float  e1 = E1[k];
            float4 hv = hB4[(size_t)sidx[k]*16 + c4];
            acc.x = fmaf(e1, hv.x, acc.x); acc.y = fmaf(e1, hv.y, acc.y);
            acc.z = fmaf(e1, hv.z, acc.z); acc.w = fmaf(e1, hv.w, acc.w);
            accs += e1;
            SgeH4[(size_t)k*16 + c4] = acc;
            if (c4 == 0) Sge1[k] = accs;
        }
    }
}

// ---------------- K4: per-row threshold lookup + combine ----------------
__global__ void k4_out(float* __restrict__ out)
{
    int gw   = (blockIdx.x * blockDim.x + threadIdx.x) >> 5;
    int lane = threadIdx.x & 31;
    if (gw >= BB*NN) return;
    int b = gw >> 12;

    float s1v = g_s1[gw];
    float M2  = g_M2[b];
    float thr = -s1v;

    const float* sval = g_sval + b*NN;
    int lo = 0, hi = NN;
    while (lo < hi) {
        int mid = (lo + hi) >> 1;
        if (sval[mid] < thr) lo = mid + 1; else hi = mid;
    }
    int k = lo;

    float x = s1v + M2;
    float m = (x >= 0.f) ? x : ALPHA * x;       // row max of lrelu logits
    float cge = __expf(x - m);                  // pairs with E1 = exp(s2 - M2)
    float clt = __expf(ALPHA * s1v - m);        // pairs with E2 = exp(alpha*s2)

    const float* SgeH = g_SgeH + ((size_t)b*(NN+1) + k)*64;
    const float* SltH = g_SltH + ((size_t)b*(NN+1) + k)*64;
    float denom = cge * g_Sge1[b*(NN+1) + k] + clt * g_Slt1[b*(NN+1) + k];
    float inv = 1.f / denom;

    float ge0 = SgeH[2*lane],   ge1 = SgeH[2*lane+1];
    float lt0 = SltH[2*lane],   lt1 = SltH[2*lane+1];
    float o0 = (cge*ge0 + clt*lt0) * inv;
    float o1 = (cge*ge1 + clt*lt1) * inv;

    float2* op = (float2*)(out + (size_t)gw*64);
    op[lane] = make_float2(o0, o1);
}

// ---------------- launch ----------------
extern "C" void kernel_launch(void* const* d_in, const int* in_sizes, int n_in,
                              void* d_out, int out_size)
{
    const float* feat = (const float*)d_in[0];
    // d_in[1] = adj: unused by the reference computation — deliberately not read.
    const float* W    = (const float*)d_in[2];
    const float* a    = (const float*)d_in[3];
    float* out = (float*)d_out;

    k1_hsw<<<(BB*NN)/16, 256>>>(feat, W, a);
    k2a_sort_runs<<<BB*NRUN, 128>>>();
    k2b_rank<<<BB*NN/256, 256>>>();
    k3a_partial<<<BB*G/8, 128>>>();
    k3b_offsets<<<BB*17, 256>>>();
    k3c_tables<<<2*BB*G/8, 128>>>();
    k4_out<<<(BB*NN*32)/256, 256>>>(out);
}